// round 5
// baseline (speedup 1.0000x reference)
#include <cuda_runtime.h>
#include <cuda_bf16.h>

// N=131072 rows, output (N,4) f32. JAX bisection bbox relabel, BETA=1.
// R5: three homogeneous task queues (A = r/l branchA 1-slot, B = r/l branchB
// 4-slot, C = both-mode 4+1-slot) solved as contiguous segments of one kernel;
// A-segment packs 4 independent tasks per thread for ILP. C-mode side
// classification done properly (each side independently B / A / neither->w0).

#define NROWS 131072
#define TOTAL (2 * NROWS)
#define BISECT_ITERS 34
#define E_F 2.718281828459045f
#define INV_E_F 0.36787944117144233f
#define SMALL_TH 5.656854249492380f   // 4*sqrt(2)

__device__ int g_cnt[3];              // nA, nB, nC
__device__ int g_listA[TOTAL];
__device__ int g_listB[TOTAL];
__device__ int g_listC[TOTAL];

__device__ __forceinline__ float flog(float w) {
    return logf(fmaxf(w, 1e-12f));    // accurate; selections only
}
__device__ __forceinline__ float smooth_l1(float x) {
    float d = fabsf(x);
    return d < 1.0f ? 0.5f * d * d : d - 0.5f;
}
__device__ __forceinline__ float eps_val(float w, float wh, float lwp) {
    return smooth_l1((w - wh) * 0.5f) + smooth_l1(flog(w) - lwp);
}

// Sign-carrying eval of eps_prime * max(w,1e-12) (positive scale) without log:
// outside [wpc/e, e*wpc] the log term saturates (+-1); inside,
// sign(t + log(mh/wpc)) == sign(mh*e^t - wpc): one MUFU.EX2. Middle-band
// derivative bounded below -> no error amplification. sigma flips sign at m<0.
__device__ __forceinline__ float bis_g(float m, float wh, float wpc,
                                       float hi, float lo, bool sigma) {
    float mh = fmaxf(m, 1e-12f);
    float cA = fminf(fmaxf((m - wh) * 0.5f, -1.0f), 1.0f);
    float t  = 0.5f * cA * mh;
    float g;
    if (mh >= hi)      g = t + 1.0f;
    else if (mh <= lo) g = t - 1.0f;
    else               g = fmaf(mh, __expf(t), -wpc);
    if (sigma && m < 0.0f) g = -g;
    return g;
}

// One bisection step + endpoint-corrected result for a single slot.
struct Slot { float u, v, u0, v0, wh, wpc, hi, lo; bool sig; };

__device__ __forceinline__ void slot_init(Slot& s, float u0, float v0,
                                          float wh, float wpc, bool sig) {
    s.u = s.u0 = u0; s.v = s.v0 = v0; s.wh = wh; s.wpc = wpc;
    s.hi = E_F * wpc; s.lo = INV_E_F * wpc; s.sig = sig;
}
__device__ __forceinline__ void slot_step(Slot& s) {
    float m = (s.u + s.v) * 0.5f;
    bool c = bis_g(m, s.wh, s.wpc, s.hi, s.lo, s.sig) >= 0.0f;
    s.v = c ? m : s.v;
    s.u = c ? s.u : m;
}
__device__ __forceinline__ float slot_result(const Slot& s) {
    float m  = (s.u + s.v) * 0.5f;
    float fu = bis_g(s.u0, s.wh, s.wpc, s.hi, s.lo, s.sig);
    float fv = bis_g(s.v0, s.wh, s.wpc, s.hi, s.lo, s.sig);
    return (fu >= 0.0f) ? s.u0 : ((fv <= 0.0f) ? s.v0 : m);
}

// branchB: init 4 slots (c2, c3, c4|c5, c6) sharing (wp, wh, w0).
__device__ __forceinline__ void initB(Slot* s, float wp, float wh, float w0,
                                      bool& smallB) {
    float wpc = fmaxf(wp, 1e-12f);
    float base = fmaxf(w0, fmaxf(wh - 2.0f, E_F * wp));
    float disc = sqrtf(fmaxf(1.0f - 32.0f / fmaxf(wh * wh, 1e-12f), 0.0f));
    float ebwp = E_F * wp;
    smallB = (wh <= SMALL_TH);
    slot_init(s[0], fmaxf(w0, wp),   fminf(ebwp, wh), wh, wpc, false);  // c2
    slot_init(s[1], fmaxf(base, 2.0f), wh,            wh, wpc, false);  // c3
    if (smallB) {
        slot_init(s[2], base, fminf(E_F, wh),         wh, wpc, true);   // c4
        slot_init(s[3], 1.0f, 1.0f,                   wh, wpc, true);   // dummy
    } else {
        slot_init(s[2], base,
                  fminf(fminf(ebwp, wh), wh * 0.25f * (1.0f + disc)),
                  wh, wpc, true);                                       // c5
        slot_init(s[3], fmaxf(base, wh * 0.25f * (1.0f - disc)),
                  fminf(ebwp, wh), wh, wpc, true);                      // c6
    }
}

// branchB argmin over [w0, wh, c2, c3, c4|c5, c6(!small)]
__device__ __forceinline__ float argminB(const float* r, float wp, float wh,
                                         float w0, bool smallB) {
    float lwp = logf(fmaxf(wp, 1e-12f));
    float bv = eps_val(w0, wh, lwp), bw = w0;
    float e1 = eps_val(wh,  wh, lwp); if (e1 < bv) { bv = e1; bw = wh;   }
    float e2 = eps_val(r[0], wh, lwp); if (e2 < bv) { bv = e2; bw = r[0]; }
    float e3 = eps_val(r[1], wh, lwp); if (e3 < bv) { bv = e3; bw = r[1]; }
    float e4 = eps_val(r[2], wh, lwp); if (e4 < bv) { bv = e4; bw = r[2]; }
    if (!smallB) {
        float e5 = eps_val(r[3], wh, lwp); if (e5 < bv) { bv = e5; bw = r[3]; }
    }
    return bw;
}

// ---------------- classify: resolve trivial, enqueue into 3 lists ---------
__global__ void k_classify(const float* __restrict__ pred,
                           const float* __restrict__ target,
                           const float* __restrict__ crop,
                           const float* __restrict__ prop,
                           const int*   __restrict__ cases,
                           float*       __restrict__ out) {
    int t = blockIdx.x * blockDim.x + threadIdx.x;
    int list = -1;   // 0=A 1=B 2=C
    int tag = 0;
    if (t < TOTAL) {
        int i = t >> 1, a = t & 1;
        int lt = cases[i * 4 + 2 * a + 0];
        int rb = cases[i * 4 + 2 * a + 1];
        int type = (lt ? 2 : 0) | (rb ? 1 : 0);   // 0=none 1=r 2=l 3=both

        if (type == 0) {
            out[i * 4 + a]     = target[i * 4 + a];
            out[i * 4 + 2 + a] = expf(target[i * 4 + 2 + a]);
        } else {
            float pd = pred[i * 4 + a];
            float td = target[i * 4 + a];
            float to = expf(target[i * 4 + 2 + a]);
            float p_d = prop[i * 4 + a];
            float p_o = prop[i * 4 + 2 + a];
            float ca = 0.5f * (p_d + p_o);
            float da = p_o - p_d;
            float cropa = crop[i * 4 + a];

            if (type != 3) {
                float po = expf(pred[i * 4 + 2 + a]);
                float a1, b1, wh;
                if (type == 1) { a1 = td - 0.5f * to; b1 = (cropa - ca) / da; wh = 2.0f * (pd - a1); }
                else           { a1 = -ca / da;       b1 = td + 0.5f * to;   wh = 2.0f * (b1 - pd); }
                float w0 = b1 - a1;
                bool bA = fmaxf(w0, wh) < po;
                bool bB = fmaxf(w0, po) < wh;
                if (!bA && !bB) {
                    float d = (type == 1) ? (a1 + 0.5f * w0) : (b1 - 0.5f * w0);
                    out[i * 4 + a]     = d;
                    out[i * 4 + 2 + a] = w0;
                } else {
                    list = bA ? 0 : 1;
                    tag = (t << 1) | (type - 1);
                }
            } else {
                float a2 = -ca / da;
                float b2 = (cropa - ca) / da;
                float wh1 = 2.0f * (pd - a2);
                float wh2 = 2.0f * (b2 - pd);
                if (pd >= fmaxf(wh1, wh2)) {          // trivial (wp = dp = pd)
                    out[i * 4 + a]     = pd;
                    out[i * 4 + 2 + a] = pd;
                } else {
                    float w0 = b2 - a2;
                    bool A1 = fmaxf(w0, wh1) < pd, B1 = fmaxf(w0, pd) < wh1;
                    bool A2 = fmaxf(w0, wh2) < pd, B2 = fmaxf(w0, pd) < wh2;
                    if (!(A1 | B1 | A2 | B2)) {       // both sides -> w0
                        float lwp = logf(fmaxf(pd, 1e-12f));
                        bool pick1 = eps_val(w0, wh1, lwp) <= eps_val(w0, wh2, lwp);
                        float d = pick1 ? (a2 + 0.5f * w0) : (b2 + 0.5f * w0);
                        out[i * 4 + a]     = d;
                        out[i * 4 + 2 + a] = w0;
                    } else { list = 2; tag = t; }
                }
            }
        }
    }
#pragma unroll
    for (int L = 0; L < 3; L++) {
        unsigned m = __ballot_sync(0xffffffffu, list == L);
        if (list == L) {
            int lane = threadIdx.x & 31;
            int leader = __ffs(m) - 1;
            int base = 0;
            if (lane == leader) base = atomicAdd(&g_cnt[L], __popc(m));
            base = __shfl_sync(m, base, leader);
            int* dst = (L == 0) ? g_listA : (L == 1) ? g_listB : g_listC;
            dst[base + __popc(m & ((1u << lane) - 1u))] = tag;
        }
    }
}

// helper: r/l geometry from tag
__device__ __forceinline__ void rl_geom(const float* pred, const float* target,
                                        const float* crop, const float* prop,
                                        int tag, int& i, int& a, int& mode,
                                        float& po, float& a1, float& b1, float& wh) {
    int t = tag >> 1; mode = (tag & 1) + 1;   // 1=r 2=l
    i = t >> 1; a = t & 1;
    float pd = pred[i * 4 + a];
    po = expf(pred[i * 4 + 2 + a]);
    float td = target[i * 4 + a];
    float to = expf(target[i * 4 + 2 + a]);
    float p_d = prop[i * 4 + a];
    float p_o = prop[i * 4 + 2 + a];
    float ca = 0.5f * (p_d + p_o);
    float da = p_o - p_d;
    float cropa = crop[i * 4 + a];
    if (mode == 1) { a1 = td - 0.5f * to; b1 = (cropa - ca) / da; wh = 2.0f * (pd - a1); }
    else           { a1 = -ca / da;       b1 = td + 0.5f * to;   wh = 2.0f * (b1 - pd); }
}

// ---------------- solve: segmented [A(4/thread) | B | C] ------------------
__global__ void k_solve(const float* __restrict__ pred,
                        const float* __restrict__ target,
                        const float* __restrict__ crop,
                        const float* __restrict__ prop,
                        float*       __restrict__ out) {
    int j = blockIdx.x * blockDim.x + threadIdx.x;
    int nA = g_cnt[0], nB = g_cnt[1], nC = g_cnt[2];
    int tA = (nA + 3) >> 2;

    if (j < tA) {
        // ---- A segment: 4 independent 1-slot bisections per thread ----
        Slot s[4];
        int ii[4], aa[4], md[4];
        float A1v[4], B1v[4];
        bool act[4];
#pragma unroll
        for (int k = 0; k < 4; k++) {
            int idx = j + k * tA;
            act[k] = idx < nA;
            if (act[k]) {
                float po, a1, b1, wh;
                rl_geom(pred, target, crop, prop, g_listA[idx],
                        ii[k], aa[k], md[k], po, a1, b1, wh);
                float w0 = b1 - a1;
                slot_init(s[k], fmaxf(w0, wh), po, wh, fmaxf(po, 1e-12f), false);
                A1v[k] = a1; B1v[k] = b1;
            } else slot_init(s[k], 1.0f, 1.0f, 1.0f, 1.0f, false);
        }
#pragma unroll 1
        for (int it = 0; it < BISECT_ITERS; it++) {
#pragma unroll
            for (int k = 0; k < 4; k++) slot_step(s[k]);
        }
#pragma unroll
        for (int k = 0; k < 4; k++) {
            if (act[k]) {
                float w = slot_result(s[k]);
                float d = (md[k] == 1) ? (A1v[k] + 0.5f * w) : (B1v[k] - 0.5f * w);
                out[ii[k] * 4 + aa[k]]     = d;
                out[ii[k] * 4 + 2 + aa[k]] = w;
            }
        }
        return;
    }
    j -= tA;
    if (j < nB) {
        // ---- B segment: 4-slot branchB ----
        int i, a, mode;
        float po, a1, b1, wh;
        rl_geom(pred, target, crop, prop, g_listB[j], i, a, mode, po, a1, b1, wh);
        float w0 = b1 - a1;
        Slot s[4]; bool smallB;
        initB(s, po, wh, w0, smallB);
#pragma unroll 1
        for (int it = 0; it < BISECT_ITERS; it++) {
#pragma unroll
            for (int k = 0; k < 4; k++) slot_step(s[k]);
        }
        float r[4];
#pragma unroll
        for (int k = 0; k < 4; k++) r[k] = slot_result(s[k]);
        float w = argminB(r, po, wh, w0, smallB);
        float d = (mode == 1) ? (a1 + 0.5f * w) : (b1 - 0.5f * w);
        out[i * 4 + a]     = d;
        out[i * 4 + 2 + a] = w;
        return;
    }
    j -= nB;
    if (j >= nC) return;

    // ---- C segment: both-mode, <=1 B side + <=1 A side ----
    int t = g_listC[j];
    int i = t >> 1, a = t & 1;
    float pd = pred[i * 4 + a];
    float p_d = prop[i * 4 + a];
    float p_o = prop[i * 4 + 2 + a];
    float ca = 0.5f * (p_d + p_o);
    float da = p_o - p_d;
    float cropa = crop[i * 4 + a];
    float a2 = -ca / da;
    float b2 = (cropa - ca) / da;
    float wh1 = 2.0f * (pd - a2);
    float wh2 = 2.0f * (b2 - pd);
    float w0 = b2 - a2;
    bool A1 = fmaxf(w0, wh1) < pd, B1 = fmaxf(w0, pd) < wh1;
    bool A2 = fmaxf(w0, wh2) < pd, B2 = fmaxf(w0, pd) < wh2;
    int sideB = B1 ? 1 : (B2 ? 2 : 0);    // at most one (wh1+wh2 = 2*w0)
    int sideA = A1 ? 1 : (A2 ? 2 : 0);    // A1&A2 -> trivial, excluded

    float whB = (sideB == 1) ? wh1 : wh2;
    float whA = (sideA == 1) ? wh1 : wh2;

    Slot s[5]; bool smallB = false;
    if (sideB) initB(s, pd, whB, w0, smallB);
    else {
#pragma unroll
        for (int k = 0; k < 4; k++) slot_init(s[k], 1.0f, 1.0f, 1.0f, 1.0f, false);
    }
    if (sideA) slot_init(s[4], fmaxf(w0, whA), pd, whA, fmaxf(pd, 1e-12f), false);
    else       slot_init(s[4], 1.0f, 1.0f, 1.0f, 1.0f, false);

#pragma unroll 1
    for (int it = 0; it < BISECT_ITERS; it++) {
#pragma unroll
        for (int k = 0; k < 5; k++) slot_step(s[k]);
    }
    float r[4];
#pragma unroll
    for (int k = 0; k < 4; k++) r[k] = slot_result(s[k]);
    float wBres = sideB ? argminB(r, pd, whB, w0, smallB) : w0;
    float wAres = sideA ? slot_result(s[4]) : w0;

    float w1 = (sideB == 1) ? wBres : ((sideA == 1) ? wAres : w0);
    float w2 = (sideB == 2) ? wBres : ((sideA == 2) ? wAres : w0);
    float lwp = logf(fmaxf(pd, 1e-12f));
    bool pick1 = eps_val(w1, wh1, lwp) <= eps_val(w2, wh2, lwp);
    float d = pick1 ? (a2 + 0.5f * w1) : (b2 + 0.5f * w2);
    float w = pick1 ? w1 : w2;
    out[i * 4 + a]     = d;
    out[i * 4 + 2 + a] = w;
}

extern "C" void kernel_launch(void* const* d_in, const int* in_sizes, int n_in,
                              void* d_out, int out_size) {
    // metadata order: img, pred, target, crop_shapes, proposal_list, cases, ...
    const float* pred   = (const float*)d_in[1];
    const float* target = (const float*)d_in[2];
    const float* crop   = (const float*)d_in[3];
    const float* prop   = (const float*)d_in[4];
    const int*   cases  = (const int*)d_in[5];
    float* out = (float*)d_out;

    void* cnt_ptr = nullptr;
    cudaGetSymbolAddress(&cnt_ptr, g_cnt);
    cudaMemsetAsync(cnt_ptr, 0, 3 * sizeof(int));

    const int block = 256;
    const int grid  = (TOTAL + block - 1) / block;
    k_classify<<<grid, block>>>(pred, target, crop, prop, cases, out);
    k_solve<<<grid, block>>>(pred, target, crop, prop, out);
}

// round 6
// speedup vs baseline: 1.1270x; 1.1270x over previous
#include <cuda_runtime.h>
#include <cuda_bf16.h>

// N=131072 rows, output (N,4) f32. JAX bisection bbox relabel, BETA=1.
// R6: slot-parallel solve. B/C tasks = quads (4 threads, 1 bisection slot
// each; C quads also step the shared A-slot); argmin over candidates via
// shfl_xor reduction on (eps, rank) = exact first-occurrence argmin.
// A tasks = 1 thread each. Raises occupancy ~4x over task-per-thread.

#define NROWS 131072
#define TOTAL (2 * NROWS)
#define BISECT_ITERS 34
#define E_F 2.718281828459045f
#define INV_E_F 0.36787944117144233f
#define SMALL_TH 5.656854249492380f   // 4*sqrt(2)

__device__ int g_cnt[3];              // nA, nB, nC
__device__ int g_listA[TOTAL];
__device__ int g_listB[TOTAL];
__device__ int g_listC[TOTAL];

__device__ __forceinline__ float smooth_l1(float x) {
    float d = fabsf(x);
    return d < 1.0f ? 0.5f * d * d : d - 0.5f;
}
__device__ __forceinline__ float eps_val(float w, float wh, float lwp) {
    return smooth_l1((w - wh) * 0.5f) + smooth_l1(logf(fmaxf(w, 1e-12f)) - lwp);
}

// Sign-carrying eval of eps_prime * max(w,1e-12) without log (band-saturated
// clip outside [wpc/e, e*wpc]; inside, sign(t+log(mh/wpc)) == sign(mh*e^t-wpc),
// one MUFU.EX2; bounded derivative -> no amplification). sigma flips at m<0.
__device__ __forceinline__ float bis_g(float m, float wh, float wpc,
                                       float hi, float lo, bool sigma) {
    float mh = fmaxf(m, 1e-12f);
    float cA = fminf(fmaxf((m - wh) * 0.5f, -1.0f), 1.0f);
    float t  = 0.5f * cA * mh;
    float g;
    if (mh >= hi)      g = t + 1.0f;
    else if (mh <= lo) g = t - 1.0f;
    else               g = fmaf(mh, __expf(t), -wpc);
    if (sigma && m < 0.0f) g = -g;
    return g;
}

struct Slot { float u, v, u0, v0, wh, wpc, hi, lo; bool sig; };

__device__ __forceinline__ void slot_init(Slot& s, float u0, float v0,
                                          float wh, float wpc, bool sig) {
    s.u = s.u0 = u0; s.v = s.v0 = v0; s.wh = wh; s.wpc = wpc;
    s.hi = E_F * wpc; s.lo = INV_E_F * wpc; s.sig = sig;
}
__device__ __forceinline__ void slot_step(Slot& s) {
    float m = (s.u + s.v) * 0.5f;
    bool c = bis_g(m, s.wh, s.wpc, s.hi, s.lo, s.sig) >= 0.0f;
    s.v = c ? m : s.v;
    s.u = c ? s.u : m;
}
__device__ __forceinline__ float slot_result(const Slot& s) {
    float m  = (s.u + s.v) * 0.5f;
    float fu = bis_g(s.u0, s.wh, s.wpc, s.hi, s.lo, s.sig);
    float fv = bis_g(s.v0, s.wh, s.wpc, s.hi, s.lo, s.sig);
    return (fu >= 0.0f) ? s.u0 : ((fv <= 0.0f) ? s.v0 : m);
}

// branchB slot k of {c2, c3, c4|c5, c6}: shared (wp, wh, w0).
__device__ __forceinline__ void initB_k(Slot& s, int k, float wp, float wh,
                                        float w0, bool& smallB) {
    float wpc = fmaxf(wp, 1e-12f);
    float base = fmaxf(w0, fmaxf(wh - 2.0f, E_F * wp));
    float disc = sqrtf(fmaxf(1.0f - 32.0f / fmaxf(wh * wh, 1e-12f), 0.0f));
    float ebwp = E_F * wp;
    smallB = (wh <= SMALL_TH);
    float u, v; bool sig;
    if (k == 0)      { u = fmaxf(w0, wp);    v = fminf(ebwp, wh); sig = false; }
    else if (k == 1) { u = fmaxf(base, 2.0f); v = wh;             sig = false; }
    else if (k == 2) {
        if (smallB) { u = base; v = fminf(E_F, wh); }
        else        { u = base; v = fminf(fminf(ebwp, wh), wh * 0.25f * (1.0f + disc)); }
        sig = true;
    } else {
        if (smallB) { u = 1.0f; v = 1.0f; }
        else        { u = fmaxf(base, wh * 0.25f * (1.0f - disc)); v = fminf(ebwp, wh); }
        sig = true;
    }
    slot_init(s, u, v, wh, wpc, sig);
}

// ---------------- classify: resolve trivial, enqueue into 3 lists ---------
__global__ void k_classify(const float* __restrict__ pred,
                           const float* __restrict__ target,
                           const float* __restrict__ crop,
                           const float* __restrict__ prop,
                           const int*   __restrict__ cases,
                           float*       __restrict__ out) {
    int t = blockIdx.x * blockDim.x + threadIdx.x;
    int list = -1;   // 0=A 1=B 2=C
    int tag = 0;
    if (t < TOTAL) {
        int i = t >> 1, a = t & 1;
        int lt = cases[i * 4 + 2 * a + 0];
        int rb = cases[i * 4 + 2 * a + 1];
        int type = (lt ? 2 : 0) | (rb ? 1 : 0);   // 0=none 1=r 2=l 3=both

        if (type == 0) {
            out[i * 4 + a]     = target[i * 4 + a];
            out[i * 4 + 2 + a] = expf(target[i * 4 + 2 + a]);
        } else {
            float pd = pred[i * 4 + a];
            float td = target[i * 4 + a];
            float to = expf(target[i * 4 + 2 + a]);
            float p_d = prop[i * 4 + a];
            float p_o = prop[i * 4 + 2 + a];
            float ca = 0.5f * (p_d + p_o);
            float da = p_o - p_d;
            float cropa = crop[i * 4 + a];

            if (type != 3) {
                float po = expf(pred[i * 4 + 2 + a]);
                float a1, b1, wh;
                if (type == 1) { a1 = td - 0.5f * to; b1 = (cropa - ca) / da; wh = 2.0f * (pd - a1); }
                else           { a1 = -ca / da;       b1 = td + 0.5f * to;   wh = 2.0f * (b1 - pd); }
                float w0 = b1 - a1;
                bool bA = fmaxf(w0, wh) < po;
                bool bB = fmaxf(w0, po) < wh;
                if (!bA && !bB) {
                    float d = (type == 1) ? (a1 + 0.5f * w0) : (b1 - 0.5f * w0);
                    out[i * 4 + a]     = d;
                    out[i * 4 + 2 + a] = w0;
                } else {
                    list = bA ? 0 : 1;
                    tag = (t << 1) | (type - 1);
                }
            } else {
                float a2 = -ca / da;
                float b2 = (cropa - ca) / da;
                float wh1 = 2.0f * (pd - a2);
                float wh2 = 2.0f * (b2 - pd);
                if (pd >= fmaxf(wh1, wh2)) {          // trivial (wp = dp = pd)
                    out[i * 4 + a]     = pd;
                    out[i * 4 + 2 + a] = pd;
                } else {
                    float w0 = b2 - a2;
                    bool A1 = fmaxf(w0, wh1) < pd, B1 = fmaxf(w0, pd) < wh1;
                    bool A2 = fmaxf(w0, wh2) < pd, B2 = fmaxf(w0, pd) < wh2;
                    if (!(A1 | B1 | A2 | B2)) {       // both sides -> w0
                        float lwp = logf(fmaxf(pd, 1e-12f));
                        bool pick1 = eps_val(w0, wh1, lwp) <= eps_val(w0, wh2, lwp);
                        float d = pick1 ? (a2 + 0.5f * w0) : (b2 + 0.5f * w0);
                        out[i * 4 + a]     = d;
                        out[i * 4 + 2 + a] = w0;
                    } else { list = 2; tag = t; }
                }
            }
        }
    }
#pragma unroll
    for (int L = 0; L < 3; L++) {
        unsigned m = __ballot_sync(0xffffffffu, list == L);
        if (list == L) {
            int lane = threadIdx.x & 31;
            int leader = __ffs(m) - 1;
            int base = 0;
            if (lane == leader) base = atomicAdd(&g_cnt[L], __popc(m));
            base = __shfl_sync(m, base, leader);
            int* dst = (L == 0) ? g_listA : (L == 1) ? g_listB : g_listC;
            dst[base + __popc(m & ((1u << lane) - 1u))] = tag;
        }
    }
}

// r/l geometry from tag
__device__ __forceinline__ void rl_geom(const float* pred, const float* target,
                                        const float* crop, const float* prop,
                                        int tag, int& i, int& a, int& mode,
                                        float& po, float& a1, float& b1, float& wh) {
    int t = tag >> 1; mode = (tag & 1) + 1;   // 1=r 2=l
    i = t >> 1; a = t & 1;
    float pd = pred[i * 4 + a];
    po = expf(pred[i * 4 + 2 + a]);
    float td = target[i * 4 + a];
    float to = expf(target[i * 4 + 2 + a]);
    float p_d = prop[i * 4 + a];
    float p_o = prop[i * 4 + 2 + a];
    float ca = 0.5f * (p_d + p_o);
    float da = p_o - p_d;
    float cropa = crop[i * 4 + a];
    if (mode == 1) { a1 = td - 0.5f * to; b1 = (cropa - ca) / da; wh = 2.0f * (pd - a1); }
    else           { a1 = -ca / da;       b1 = td + 0.5f * to;   wh = 2.0f * (b1 - pd); }
}

// ---------------- solve: [A singles | quad region (B then C)] -------------
__global__ void k_solve(const float* __restrict__ pred,
                        const float* __restrict__ target,
                        const float* __restrict__ crop,
                        const float* __restrict__ prop,
                        float*       __restrict__ out) {
    int nA = g_cnt[0], nB = g_cnt[1], nC = g_cnt[2];
    int qbase = (nA + 31) & ~31;            // 32-aligned quad-region start
    int nQ = nB + nC;
    int needTotal = qbase + 4 * nQ;
    int lane = threadIdx.x & 31;
    int stride = gridDim.x * blockDim.x;

    for (int wbase = blockIdx.x * blockDim.x + ((int)threadIdx.x & ~31);
         wbase < needTotal; wbase += stride) {
        int j = wbase + lane;

        if (wbase < qbase) {
            // -------- A warp: 1-slot tasks, no shfl --------
            if (j < nA) {
                int i, a, mode;
                float po, a1, b1, wh;
                rl_geom(pred, target, crop, prop, g_listA[j], i, a, mode, po, a1, b1, wh);
                float w0 = b1 - a1;
                Slot s;
                slot_init(s, fmaxf(w0, wh), po, wh, fmaxf(po, 1e-12f), false);
#pragma unroll 1
                for (int it = 0; it < BISECT_ITERS; it++) slot_step(s);
                float w = slot_result(s);
                float d = (mode == 1) ? (a1 + 0.5f * w) : (b1 - 0.5f * w);
                out[i * 4 + a]     = d;
                out[i * 4 + 2 + a] = w;
            }
            continue;
        }

        // -------- quad warp --------
        int q  = (j - wbase) / 4 + (wbase - qbase) / 4;   // == (j-qbase)>>2
        if (((wbase - qbase) >> 2) >= nQ) continue;        // whole warp invalid
        bool valid = q < nQ;
        bool isC   = valid && (q >= nB);
        int  kslot = j & 3;

        // task params
        int  i = 0, a = 0, mode = 0;
        float a1 = 0.f, b1 = 0.f;                   // r/l
        float a2 = 0.f, b2 = 0.f, wh1 = 1.f, wh2 = 1.f, pdC = 1.f;
        int  sb = 0, sa = 0;                        // C side indices (0/1/2)
        float w0 = 1.f, whB = 1.f, wpq = 1.f, whA = 1.f;
        bool hasB = false, smallB = false;

        Slot sB, sA;
        slot_init(sB, 1.0f, 1.0f, 1.0f, 1.0f, false);
        slot_init(sA, 1.0f, 1.0f, 1.0f, 1.0f, false);

        if (valid && !isC) {
            float po, wh;
            rl_geom(pred, target, crop, prop, g_listB[q], i, a, mode, po, a1, b1, wh);
            w0 = b1 - a1; whB = wh; wpq = po; hasB = true;
            initB_k(sB, kslot, po, wh, w0, smallB);
        } else if (valid) {
            int t = g_listC[q - nB];
            i = t >> 1; a = t & 1;
            float pd = pred[i * 4 + a];
            float p_d = prop[i * 4 + a];
            float p_o = prop[i * 4 + 2 + a];
            float ca = 0.5f * (p_d + p_o);
            float da = p_o - p_d;
            float cropa = crop[i * 4 + a];
            a2 = -ca / da;
            b2 = (cropa - ca) / da;
            wh1 = 2.0f * (pd - a2);
            wh2 = 2.0f * (b2 - pd);
            w0 = b2 - a2; pdC = pd; wpq = pd;
            bool A1 = fmaxf(w0, wh1) < pd, B1 = fmaxf(w0, pd) < wh1;
            bool A2 = fmaxf(w0, wh2) < pd, B2 = fmaxf(w0, pd) < wh2;
            sb = B1 ? 1 : (B2 ? 2 : 0);             // at most one B side
            sa = A1 ? 1 : (A2 ? 2 : 0);
            whB = (sb == 1) ? wh1 : wh2;
            whA = (sa == 1) ? wh1 : wh2;
            hasB = (sb != 0);
            if (hasB) initB_k(sB, kslot, pd, whB, w0, smallB);
            if (sa)   slot_init(sA, fmaxf(w0, whA), pd, whA, fmaxf(pd, 1e-12f), false);
        }

        bool anyC = __any_sync(0xffffffffu, isC);
#pragma unroll 1
        for (int it = 0; it < BISECT_ITERS; it++) {
            slot_step(sB);
            if (anyC) slot_step(sA);
        }

        // per-lane candidates: base (lane0:w0 rank0, lane1:whB rank1) and
        // slot result (k0:c2 rank2, k1:c3 rank3, k2:c4|c5 rank4|5, k3:c6 rank6)
        float rB  = slot_result(sB);
        float lwp = logf(fmaxf(wpq, 1e-12f));
        bool bOK  = valid && hasB;

        float baseW = (kslot == 0) ? w0 : whB;
        float epsBase = (bOK && kslot < 2) ? eps_val(baseW, whB, lwp) : 1e30f;
        int   rankBase = kslot;                                 // 0 or 1 (else dead)

        bool slotDead = (kslot == 3 && smallB);
        float epsSlot = (bOK && !slotDead) ? eps_val(rB, whB, lwp) : 1e30f;
        int   rankSlot = (kslot == 2) ? (smallB ? 4 : 5) : (kslot == 0 ? 2 : (kslot == 1 ? 3 : 6));

        float be, bw; int br;
        if (epsSlot < epsBase || (epsSlot == epsBase && rankSlot < rankBase)) {
            be = epsSlot; bw = rB; br = rankSlot;
        } else {
            be = epsBase; bw = baseW; br = rankBase;
        }
#pragma unroll
        for (int dlt = 1; dlt <= 2; dlt <<= 1) {
            float oe = __shfl_xor_sync(0xffffffffu, be, dlt);
            float ow = __shfl_xor_sync(0xffffffffu, bw, dlt);
            int   orr = __shfl_xor_sync(0xffffffffu, br, dlt);
            if (oe < be || (oe == be && orr < br)) { be = oe; bw = ow; br = orr; }
        }

        if (valid && kslot == 0) {
            if (!isC) {
                float w = bw;
                float d = (mode == 1) ? (a1 + 0.5f * w) : (b1 - 0.5f * w);
                out[i * 4 + a]     = d;
                out[i * 4 + 2 + a] = w;
            } else {
                float wB = hasB ? bw : w0;
                float wA = sa ? slot_result(sA) : w0;
                float w1 = (sb == 1) ? wB : ((sa == 1) ? wA : w0);
                float w2 = (sb == 2) ? wB : ((sa == 2) ? wA : w0);
                float lwpC = logf(fmaxf(pdC, 1e-12f));
                bool pick1 = eps_val(w1, wh1, lwpC) <= eps_val(w2, wh2, lwpC);
                float d = pick1 ? (a2 + 0.5f * w1) : (b2 + 0.5f * w2);
                float w = pick1 ? w1 : w2;
                out[i * 4 + a]     = d;
                out[i * 4 + 2 + a] = w;
            }
        }
    }
}

extern "C" void kernel_launch(void* const* d_in, const int* in_sizes, int n_in,
                              void* d_out, int out_size) {
    // metadata order: img, pred, target, crop_shapes, proposal_list, cases, ...
    const float* pred   = (const float*)d_in[1];
    const float* target = (const float*)d_in[2];
    const float* crop   = (const float*)d_in[3];
    const float* prop   = (const float*)d_in[4];
    const int*   cases  = (const int*)d_in[5];
    float* out = (float*)d_out;

    void* cnt_ptr = nullptr;
    cudaGetSymbolAddress(&cnt_ptr, g_cnt);
    cudaMemsetAsync(cnt_ptr, 0, 3 * sizeof(int));

    const int block = 256;
    const int gridC = (TOTAL + block - 1) / block;
    k_classify<<<gridC, block>>>(pred, target, crop, prop, cases, out);
    k_solve<<<2048, block>>>(pred, target, crop, prop, out);
}

// round 7
// speedup vs baseline: 1.9863x; 1.7624x over previous
#include <cuda_runtime.h>
#include <cuda_bf16.h>

// N=131072 rows, output (N,4) f32. JAX bisection bbox relabel, BETA=1.
// R7: ONE fused kernel. Each thread classifies one (row,axis) task; ~95% are
// analytically trivial and finish inline. Non-trivial tasks are compacted
// into block-shared lists (geometry cached in smem, one descriptor per
// independent bisection slot); slot phase runs the 34-iter bisections
// slot-parallel; finalize phase does the exact-order argmin / pick1.
// No global scratch, no memset node, single launch.

#define NROWS 131072
#define TOTAL (2 * NROWS)
#define BLOCK 256
#define BISECT_ITERS 34
#define E_F 2.718281828459045f
#define INV_E_F 0.36787944117144233f
#define SMALL_TH 5.656854249492380f   // 4*sqrt(2)

// flag bits
#define F_ISC    1
#define F_RLL    2     // r/l: left mode
#define F_HASB   4
#define F_SMALL  8
#define F_SB1    16    // C: B side is side1
#define F_SB2    32
#define F_SA1    64    // C: A side is side1
#define F_SA2    128

__device__ __forceinline__ float smooth_l1(float x) {
    float d = fabsf(x);
    return d < 1.0f ? 0.5f * d * d : d - 0.5f;
}
__device__ __forceinline__ float eps_val(float w, float wh, float lwp) {
    return smooth_l1((w - wh) * 0.5f) + smooth_l1(logf(fmaxf(w, 1e-12f)) - lwp);
}

// Sign-carrying eval of eps_prime * max(w,1e-12) without log (clip saturates
// outside [wpc/e, e*wpc]; inside, sign(t+log(mh/wpc)) == sign(mh*e^t - wpc):
// one MUFU.EX2, derivative bounded below -> no amplification). sigma: flip at m<0.
__device__ __forceinline__ float bis_g(float m, float wh, float wpc,
                                       float hi, float lo, bool sigma) {
    float mh = fmaxf(m, 1e-12f);
    float cA = fminf(fmaxf((m - wh) * 0.5f, -1.0f), 1.0f);
    float t  = 0.5f * cA * mh;
    float g;
    if (mh >= hi)      g = t + 1.0f;
    else if (mh <= lo) g = t - 1.0f;
    else               g = fmaf(mh, __expf(t), -wpc);
    if (sigma && m < 0.0f) g = -g;
    return g;
}

struct Slot { float u, v, u0, v0, wh, wpc, hi, lo; bool sig; };

__device__ __forceinline__ void slot_init(Slot& s, float u0, float v0,
                                          float wh, float wpc, bool sig) {
    s.u = s.u0 = u0; s.v = s.v0 = v0; s.wh = wh; s.wpc = wpc;
    s.hi = E_F * wpc; s.lo = INV_E_F * wpc; s.sig = sig;
}
__device__ __forceinline__ void slot_step(Slot& s) {
    float m = (s.u + s.v) * 0.5f;
    bool c = bis_g(m, s.wh, s.wpc, s.hi, s.lo, s.sig) >= 0.0f;
    s.v = c ? m : s.v;
    s.u = c ? s.u : m;
}
__device__ __forceinline__ float slot_result(const Slot& s) {
    float m  = (s.u + s.v) * 0.5f;
    float fu = bis_g(s.u0, s.wh, s.wpc, s.hi, s.lo, s.sig);
    float fv = bis_g(s.v0, s.wh, s.wpc, s.hi, s.lo, s.sig);
    return (fu >= 0.0f) ? s.u0 : ((fv <= 0.0f) ? s.v0 : m);
}

// branchB slot k of {c2, c3, c4|c5, c6}: shared (wp, wh, w0).
__device__ __forceinline__ void initB_k(Slot& s, int k, float wp, float wh,
                                        float w0) {
    float wpc = fmaxf(wp, 1e-12f);
    float base = fmaxf(w0, fmaxf(wh - 2.0f, E_F * wp));
    float disc = sqrtf(fmaxf(1.0f - 32.0f / fmaxf(wh * wh, 1e-12f), 0.0f));
    float ebwp = E_F * wp;
    bool smallB = (wh <= SMALL_TH);
    float u, v; bool sig;
    if (k == 0)      { u = fmaxf(w0, wp);     v = fminf(ebwp, wh); sig = false; }  // c2
    else if (k == 1) { u = fmaxf(base, 2.0f); v = wh;              sig = false; }  // c3
    else if (k == 2) {
        if (smallB) { u = base; v = fminf(E_F, wh); }                              // c4
        else        { u = base; v = fminf(fminf(ebwp, wh), wh * 0.25f * (1.0f + disc)); } // c5
        sig = true;
    } else {
        u = fmaxf(base, wh * 0.25f * (1.0f - disc));                               // c6
        v = fminf(ebwp, wh);
        sig = true;
    }
    slot_init(s, u, v, wh, wpc, sig);
}

__global__ void __launch_bounds__(BLOCK) k_fused(
        const float* __restrict__ pred,
        const float* __restrict__ target,
        const float* __restrict__ crop,
        const float* __restrict__ prop,
        const int*   __restrict__ cases,
        float*       __restrict__ out) {
    __shared__ int   s_cnt, s_nslots;
    __shared__ int   s_flags[BLOCK];
    __shared__ int   s_task[BLOCK];          // global task id t
    __shared__ float s_wp[BLOCK], s_whB[BLOCK], s_whA[BLOCK], s_w0[BLOCK];
    __shared__ float s_p1[BLOCK], s_p2[BLOCK];     // a1,b1 (r/l) or a2,b2 (C)
    __shared__ float s_wh1[BLOCK], s_wh2[BLOCK];   // C only
    __shared__ short s_desc[BLOCK * 5];            // (local<<3)|k  (k=0..3 B, 4=A)
    __shared__ float s_res[BLOCK * 5];

    int tid = threadIdx.x;
    if (tid == 0) { s_cnt = 0; s_nslots = 0; }
    __syncthreads();

    // ---------------- phase 1: classify + trivial resolve ----------------
    int t = blockIdx.x * BLOCK + tid;
    {
        int i = t >> 1, a = t & 1;
        int lt = cases[i * 4 + 2 * a + 0];
        int rb = cases[i * 4 + 2 * a + 1];
        int type = (lt ? 2 : 0) | (rb ? 1 : 0);   // 0=none 1=r 2=l 3=both

        if (type == 0) {
            out[i * 4 + a]     = target[i * 4 + a];
            out[i * 4 + 2 + a] = expf(target[i * 4 + 2 + a]);
        } else {
            float pd = pred[i * 4 + a];
            float td = target[i * 4 + a];
            float to = expf(target[i * 4 + 2 + a]);
            float p_d = prop[i * 4 + a];
            float p_o = prop[i * 4 + 2 + a];
            float ca = 0.5f * (p_d + p_o);
            float da = p_o - p_d;
            float cropa = crop[i * 4 + a];

            if (type != 3) {
                float po = expf(pred[i * 4 + 2 + a]);
                float a1, b1, wh;
                if (type == 1) { a1 = td - 0.5f * to; b1 = (cropa - ca) / da; wh = 2.0f * (pd - a1); }
                else           { a1 = -ca / da;       b1 = td + 0.5f * to;   wh = 2.0f * (b1 - pd); }
                float w0 = b1 - a1;
                bool bA = fmaxf(w0, wh) < po;
                bool bB = fmaxf(w0, po) < wh;
                if (!bA && !bB) {
                    float d = (type == 1) ? (a1 + 0.5f * w0) : (b1 - 0.5f * w0);
                    out[i * 4 + a]     = d;
                    out[i * 4 + 2 + a] = w0;
                } else {
                    int L = atomicAdd(&s_cnt, 1);
                    int fl = (type == 2 ? F_RLL : 0);
                    s_task[L] = t;
                    s_wp[L] = po; s_w0[L] = w0;
                    s_p1[L] = a1; s_p2[L] = b1;
                    int ns;
                    int base;
                    if (bA) {
                        s_whA[L] = wh;
                        ns = 1;
                        base = atomicAdd(&s_nslots, ns);
                        s_desc[base] = (short)((L << 3) | 4);
                    } else {
                        fl |= F_HASB;
                        bool sm = (wh <= SMALL_TH);
                        if (sm) fl |= F_SMALL;
                        s_whB[L] = wh;
                        ns = sm ? 3 : 4;
                        base = atomicAdd(&s_nslots, ns);
                        for (int k = 0; k < ns; k++)
                            s_desc[base + k] = (short)((L << 3) | k);
                    }
                    s_flags[L] = fl;
                }
            } else {
                float a2 = -ca / da;
                float b2 = (cropa - ca) / da;
                float wh1 = 2.0f * (pd - a2);
                float wh2 = 2.0f * (b2 - pd);
                if (pd >= fmaxf(wh1, wh2)) {          // trivial (wp = dp = pd)
                    out[i * 4 + a]     = pd;
                    out[i * 4 + 2 + a] = pd;
                } else {
                    float w0 = b2 - a2;
                    bool A1 = fmaxf(w0, wh1) < pd, B1 = fmaxf(w0, pd) < wh1;
                    bool A2 = fmaxf(w0, wh2) < pd, B2 = fmaxf(w0, pd) < wh2;
                    if (!(A1 | B1 | A2 | B2)) {       // both sides -> w0
                        float lwp = logf(fmaxf(pd, 1e-12f));
                        bool pick1 = eps_val(w0, wh1, lwp) <= eps_val(w0, wh2, lwp);
                        float d = pick1 ? (a2 + 0.5f * w0) : (b2 + 0.5f * w0);
                        out[i * 4 + a]     = d;
                        out[i * 4 + 2 + a] = w0;
                    } else {
                        int L = atomicAdd(&s_cnt, 1);
                        int fl = F_ISC;
                        int sb = B1 ? 1 : (B2 ? 2 : 0);   // at most one B side
                        int sa = A1 ? 1 : (A2 ? 2 : 0);
                        if (sb == 1) fl |= F_SB1; else if (sb == 2) fl |= F_SB2;
                        if (sa == 1) fl |= F_SA1; else if (sa == 2) fl |= F_SA2;
                        float whB = (sb == 1) ? wh1 : wh2;
                        float whA = (sa == 1) ? wh1 : wh2;
                        s_task[L] = t;
                        s_wp[L] = pd; s_w0[L] = w0;
                        s_p1[L] = a2; s_p2[L] = b2;
                        s_wh1[L] = wh1; s_wh2[L] = wh2;
                        s_whA[L] = whA; s_whB[L] = whB;
                        int nb = 0;
                        bool sm = (whB <= SMALL_TH);
                        if (sb) { fl |= F_HASB; if (sm) fl |= F_SMALL; nb = sm ? 3 : 4; }
                        int ns = nb + (sa ? 1 : 0);
                        int base = atomicAdd(&s_nslots, ns);
                        for (int k = 0; k < nb; k++)
                            s_desc[base + k] = (short)((L << 3) | k);
                        if (sa) s_desc[base + nb] = (short)((L << 3) | 4);
                        s_flags[L] = fl;
                    }
                }
            }
        }
    }
    __syncthreads();

    // ---------------- phase 2: slot-parallel bisections -------------------
    int nslots = s_nslots;
    for (int sidx = tid; sidx < nslots; sidx += BLOCK) {
        int d = s_desc[sidx];
        int L = d >> 3, k = d & 7;
        float wp = s_wp[L], w0 = s_w0[L];
        Slot sl;
        if (k == 4) {
            float wh = s_whA[L];
            slot_init(sl, fmaxf(w0, wh), wp, wh, fmaxf(wp, 1e-12f), false);
        } else {
            initB_k(sl, k, wp, s_whB[L], w0);
        }
#pragma unroll 1
        for (int it = 0; it < BISECT_ITERS; it++) slot_step(sl);
        s_res[L * 5 + k] = slot_result(sl);
    }
    __syncthreads();

    // ---------------- phase 3: finalize -----------------------------------
    int cnt = s_cnt;
    if (tid < cnt) {
        int L = tid;
        int fl = s_flags[L];
        int tg = s_task[L];
        int i = tg >> 1, a = tg & 1;
        float wp = s_wp[L], w0 = s_w0[L];
        float lwp = logf(fmaxf(wp, 1e-12f));

        float bw = w0;
        if (fl & F_HASB) {
            float whB = s_whB[L];
            bool sm = (fl & F_SMALL);
            float bv = eps_val(w0, whB, lwp);
            float e1 = eps_val(whB, whB, lwp);
            if (e1 < bv) { bv = e1; bw = whB; }
            float e2 = eps_val(s_res[L * 5 + 0], whB, lwp);
            if (e2 < bv) { bv = e2; bw = s_res[L * 5 + 0]; }
            float e3 = eps_val(s_res[L * 5 + 1], whB, lwp);
            if (e3 < bv) { bv = e3; bw = s_res[L * 5 + 1]; }
            float e4 = eps_val(s_res[L * 5 + 2], whB, lwp);
            if (e4 < bv) { bv = e4; bw = s_res[L * 5 + 2]; }
            if (!sm) {
                float e5 = eps_val(s_res[L * 5 + 3], whB, lwp);
                if (e5 < bv) { bv = e5; bw = s_res[L * 5 + 3]; }
            }
        }

        float dres, wres;
        if (!(fl & F_ISC)) {
            wres = (fl & F_HASB) ? bw : s_res[L * 5 + 4];
            float a1 = s_p1[L], b1 = s_p2[L];
            dres = (fl & F_RLL) ? (b1 - 0.5f * wres) : (a1 + 0.5f * wres);
        } else {
            float a2 = s_p1[L], b2 = s_p2[L];
            float wh1 = s_wh1[L], wh2 = s_wh2[L];
            int sb = (fl & F_SB1) ? 1 : ((fl & F_SB2) ? 2 : 0);
            int sa = (fl & F_SA1) ? 1 : ((fl & F_SA2) ? 2 : 0);
            float wB = (fl & F_HASB) ? bw : w0;
            float wA = sa ? s_res[L * 5 + 4] : w0;
            float w1 = (sb == 1) ? wB : ((sa == 1) ? wA : w0);
            float w2 = (sb == 2) ? wB : ((sa == 2) ? wA : w0);
            bool pick1 = eps_val(w1, wh1, lwp) <= eps_val(w2, wh2, lwp);
            dres = pick1 ? (a2 + 0.5f * w1) : (b2 + 0.5f * w2);
            wres = pick1 ? w1 : w2;
        }
        out[i * 4 + a]     = dres;
        out[i * 4 + 2 + a] = wres;
    }
}

extern "C" void kernel_launch(void* const* d_in, const int* in_sizes, int n_in,
                              void* d_out, int out_size) {
    // metadata order: img, pred, target, crop_shapes, proposal_list, cases, ...
    const float* pred   = (const float*)d_in[1];
    const float* target = (const float*)d_in[2];
    const float* crop   = (const float*)d_in[3];
    const float* prop   = (const float*)d_in[4];
    const int*   cases  = (const int*)d_in[5];
    float* out = (float*)d_out;

    k_fused<<<TOTAL / BLOCK, BLOCK>>>(pred, target, crop, prop, cases, out);
}